// round 4
// baseline (speedup 1.0000x reference)
#include <cuda_runtime.h>

#define BB 512
#define TT 512
#define NS 64
#define NWARP 4               // batches (warps) per block
#define NBLK (BB / NWARP)     // 128 blocks <= 148 SMs: single wave

// sm_103a packed fp32 pipe: 2 full-precision FMAs / ADDs per instruction
#define FMA2(acc, p, e) \
    asm("fma.rn.f32x2 %0, %1, %2, %0;" : "+l"(acc) : "l"(p), "l"(e))
#define ADD2(out, a, b) \
    asm("add.rn.f32x2 %0, %1, %2;" : "=l"(out) : "l"(a), "l"(b))
#define UNPACK2(lo, hi, v) \
    asm("mov.b64 {%0, %1}, %2;" : "=r"(lo), "=r"(hi) : "l"(v))

__device__ __forceinline__ unsigned long long pack2f(float lo, float hi) {
    unsigned long long v;
    asm("mov.b64 %0, {%1, %2};" : "=l"(v) : "r"(__float_as_uint(lo)), "r"(__float_as_uint(hi)));
    return v;
}

__device__ int d_perm[BB];

// Rank batches by sequence length (descending): longest chains go to the
// lowest block ids -> resident from t=0 on dedicated SMSPs.
__global__ void rank_kernel(const int* __restrict__ lens) {
    __shared__ int L[BB];
    const int b = threadIdx.x;
    L[b] = lens[b];
    __syncthreads();
    const int myl = L[b];
    int r = 0;
    #pragma unroll 8
    for (int i = 0; i < BB; ++i) {
        const int li = L[i];
        r += (li > myl) || (li == myl && i < b);
    }
    d_perm[r] = b;
}

// One warp per batch; lane L owns states 2L and 2L+1. No cross-warp sync:
// state exchange is STS.64 + __syncwarp + broadcast LDS.128, all intra-warp.
__global__ __launch_bounds__(128) void crf_kernel(
    const float* __restrict__ inputs,   // [B,T,N]
    const float* __restrict__ trans,    // [N,N]
    const int*   __restrict__ tags,    // [B,T]
    const int*   __restrict__ lens,    // [B]
    float*       __restrict__ out,     // [B] ll, then [N*N] trans copy
    int write_trans)
{
    const int tid = threadIdx.x;
    const int w   = tid >> 5;   // warp in block = batch slot
    const int L   = tid & 31;   // lane

    const int bb = blockIdx.x * NWARP + w;
    const int b  = d_perm[bb];

    __shared__ __align__(16) unsigned long long s_buf[NWARP][2][32];

    if (write_trans && blockIdx.x < 32) {
        out[BB + blockIdx.x * 128 + tid] = trans[blockIdx.x * 128 + tid];
    }

    const int len  = lens[b];
    const int last = (len - 1) > 0 ? (len - 1) : 0;

    const int* tg = tags + (size_t)b * TT;
    const float* in_b = inputs + (size_t)b * TT * NS;

    // ---------------- sequence score (intra-warp) ----------------
    float sc = 0.f;
    for (int t = L; t < TT; t += 32) {
        if (t < len) {
            int yt = tg[t];
            sc += __ldg(&in_b[(size_t)t * NS + yt]);
            if (t >= 1) sc += __ldg(&trans[tg[t - 1] * NS + yt]);
        }
    }
    #pragma unroll
    for (int o = 16; o; o >>= 1) sc += __shfl_xor_sync(0xffffffffu, sc, o);
    const float seq_score = sc;   // lane-uniform after butterfly

    // ---------------- E columns 2L, 2L+1 packed by row-pairs ----------------
    // e2a[p] = (E[2p][2L],   E[2p+1][2L]  ),  e2b[p] = (E[2p][2L+1], E[2p+1][2L+1])
    unsigned long long e2a[32], e2b[32];
    const int ja = 2 * L, jb = 2 * L + 1;
    #pragma unroll
    for (int p = 0; p < 32; ++p) {
        const float r0a = __expf(__ldg(&trans[(2 * p) * NS + ja]));
        const float r1a = __expf(__ldg(&trans[(2 * p + 1) * NS + ja]));
        const float r0b = __expf(__ldg(&trans[(2 * p) * NS + jb]));
        const float r1b = __expf(__ldg(&trans[(2 * p + 1) * NS + jb]));
        e2a[p] = pack2f(r0a, r1a);
        e2b[p] = pack2f(r0b, r1b);
    }

    // ---------------- forward recurrence, scaled linear space ----------------
    const float e00 = __ldg(&in_b[0]);
    float M = e00;
    float s_lo = __expf(in_b[ja] - e00);
    float s_hi = __expf(in_b[jb] - e00);
    s_buf[w][0][L] = pack2f(s_lo, s_hi);

    const float2* in2 = (const float2*)in_b;   // emit pairs for this lane

    // prefetch pe = exp(emit - emit0) for both states, + emit0, depth 6
    float pl0 = 1.f, ph0 = 1.f, pl1 = 1.f, ph1 = 1.f, pl2 = 1.f, ph2 = 1.f;
    float pl3 = 1.f, ph3 = 1.f, pl4 = 1.f, ph4 = 1.f, pl5 = 1.f, ph5 = 1.f;
    float me0 = 0.f, me1 = 0.f, me2 = 0.f, me3 = 0.f, me4 = 0.f, me5 = 0.f;
    {
        float e0; float2 em;
        if (1 <= last) { e0 = __ldg(&in_b[1 * NS]); em = __ldg(&in2[1 * 32 + L]); pl0 = __expf(em.x - e0); ph0 = __expf(em.y - e0); me0 = e0; }
        if (2 <= last) { e0 = __ldg(&in_b[2 * NS]); em = __ldg(&in2[2 * 32 + L]); pl1 = __expf(em.x - e0); ph1 = __expf(em.y - e0); me1 = e0; }
        if (3 <= last) { e0 = __ldg(&in_b[3 * NS]); em = __ldg(&in2[3 * 32 + L]); pl2 = __expf(em.x - e0); ph2 = __expf(em.y - e0); me2 = e0; }
        if (4 <= last) { e0 = __ldg(&in_b[4 * NS]); em = __ldg(&in2[4 * 32 + L]); pl3 = __expf(em.x - e0); ph3 = __expf(em.y - e0); me3 = e0; }
        if (5 <= last) { e0 = __ldg(&in_b[5 * NS]); em = __ldg(&in2[5 * 32 + L]); pl4 = __expf(em.x - e0); ph4 = __expf(em.y - e0); me4 = e0; }
        if (6 <= last) { e0 = __ldg(&in_b[6 * NS]); em = __ldg(&in2[6 * 32 + L]); pl5 = __expf(em.x - e0); ph5 = __expf(em.y - e0); me5 = e0; }
    }

    int buf = 0;
    for (int t = 1; t <= last; ++t) {
        __syncwarp();

        // broadcast scalar s0 (lane 0, lo): rcp + M-update overlap the dot
        const float s0 = ((const float*)s_buf[w][buf])[0];
        const float r_inv = __frcp_rn(s0);

        const float pl_c = pl0, ph_c = ph0, me_c = me0;
        pl0 = pl1; ph0 = ph1; me0 = me1;
        pl1 = pl2; ph1 = ph2; me1 = me2;
        pl2 = pl3; ph2 = ph3; me2 = me3;
        pl3 = pl4; ph3 = ph4; me3 = me4;
        pl4 = pl5; ph4 = ph5; me4 = me5;
        const int tn = t + 6;
        if (tn <= last) {
            const float e0 = __ldg(&in_b[(size_t)tn * NS]);
            const float2 em = __ldg(&in2[(size_t)tn * 32 + L]);
            pl5 = __expf(em.x - e0);
            ph5 = __expf(em.y - e0);
            me5 = e0;
        }
        M += me_c + __logf(s0);

        // dot products for both owned columns: 64 FMA2, broadcast LDS.128
        const ulonglong2* p4 = (const ulonglong2*)s_buf[w][buf];
        unsigned long long A0 = 0ull, A1 = 0ull, B0 = 0ull, B1 = 0ull;
        #pragma unroll
        for (int m = 0; m < 16; ++m) {
            const ulonglong2 v = p4[m];
            FMA2(A0, v.x, e2a[2 * m + 0]);
            FMA2(B0, v.x, e2b[2 * m + 0]);
            FMA2(A1, v.y, e2a[2 * m + 1]);
            FMA2(B1, v.y, e2b[2 * m + 1]);
        }
        ADD2(A0, A0, A1);
        ADD2(B0, B0, B1);
        unsigned al, ah, bl, bh;
        UNPACK2(al, ah, A0);
        UNPACK2(bl, bh, B0);
        const float dotA = __uint_as_float(al) + __uint_as_float(ah);
        const float dotB = __uint_as_float(bl) + __uint_as_float(bh);

        s_lo = dotA * (pl_c * r_inv);
        s_hi = dotB * (ph_c * r_inv);
        s_buf[w][buf ^ 1][L] = pack2f(s_lo, s_hi);
        buf ^= 1;
    }

    // ---------------- final logsumexp over 64 states (intra-warp) ----------------
    const float alpha_lo = __logf(s_lo) + M;
    const float alpha_hi = __logf(s_hi) + M;

    float mx = fmaxf(alpha_lo, alpha_hi);
    #pragma unroll
    for (int o = 16; o; o >>= 1)
        mx = fmaxf(mx, __shfl_xor_sync(0xffffffffu, mx, o));

    float s = __expf(alpha_lo - mx) + __expf(alpha_hi - mx);
    #pragma unroll
    for (int o = 16; o; o >>= 1)
        s += __shfl_xor_sync(0xffffffffu, s, o);

    if (L == 0) out[b] = seq_score - (mx + __logf(s));
}

extern "C" void kernel_launch(void* const* d_in, const int* in_sizes, int n_in,
                              void* d_out, int out_size) {
    const float* inputs = (const float*)d_in[0];   // [B,T,N] f32
    const float* trans  = (const float*)d_in[1];   // [N,N]   f32
    const int*   tags   = (const int*)d_in[2];     // [B,T]   i32
    const int*   lens   = (const int*)d_in[3];     // [B]     i32
    float* out = (float*)d_out;

    const int write_trans = (out_size >= BB + NS * NS) ? 1 : 0;
    rank_kernel<<<1, BB>>>(lens);
    crf_kernel<<<NBLK, 128>>>(inputs, trans, tags, lens, out, write_trans);
}

// round 5
// speedup vs baseline: 1.4532x; 1.4532x over previous
#include <cuda_runtime.h>

#define BB 512
#define TT 512
#define NS 64

// sm_103a packed fp32 pipe: 2 full-precision fp32 FMAs / ADDs per instruction
#define FMA2(acc, p, e) \
    asm("fma.rn.f32x2 %0, %1, %2, %0;" : "+l"(acc) : "l"(p), "l"(e))
#define ADD2(out, a, b) \
    asm("add.rn.f32x2 %0, %1, %2;" : "=l"(out) : "l"(a), "l"(b))
#define UNPACK2(lo, hi, v) \
    asm("mov.b64 {%0, %1}, %2;" : "=r"(lo), "=r"(hi) : "l"(v))

__device__ int d_perm[BB];

// Rank batches by sequence length (descending). Longest chains get the lowest
// block ids (resident first, tail uncontended); adjacent pairs have matched
// lengths so the two groups in a block waste ~1 step on each other.
__global__ void rank_kernel(const int* __restrict__ lens) {
    __shared__ int L[BB];
    const int b = threadIdx.x;
    L[b] = lens[b];
    __syncthreads();
    const int myl = L[b];
    int r = 0;
    #pragma unroll 8
    for (int i = 0; i < BB; ++i) {
        const int li = L[i];
        r += (li > myl) || (li == myl && i < b);
    }
    d_perm[r] = b;
}

// 128 threads = 2 batches. Group 0 = warps 0,1 (SMSP 0,1); group 1 = warps
// 2,3 (SMSP 2,3): all 4 schedulers carry chain work. Thread j of a group owns
// state j; the 64-wide dot is split across the group's two warps (32 FMA2
// each). One plain __syncthreads per step.
__global__ __launch_bounds__(128) void crf_kernel(
    const float* __restrict__ inputs,   // [B,T,N]
    const float* __restrict__ trans,    // [N,N]
    const int*   __restrict__ tags,    // [B,T]
    const int*   __restrict__ lens,    // [B]
    float*       __restrict__ out,     // [B] ll, then [N*N] trans copy
    int write_trans)
{
    const int tid  = threadIdx.x;
    const int g    = tid >> 6;        // group (batch slot) 0/1
    const int j    = tid & 63;        // state index within group
    const int wg   = (tid >> 5) & 1;  // warp within group
    const int lane = tid & 31;

    const int b0 = d_perm[2 * blockIdx.x];
    const int b1 = d_perm[2 * blockIdx.x + 1];
    const int b  = g ? b1 : b0;

    __shared__ __align__(16) float s_buf[2][2][NS];  // [group][ping-pong][state]
    __shared__ float red[2][2];                      // [group][warp]

    if (write_trans && blockIdx.x < 32) {
        out[BB + blockIdx.x * 128 + tid] = trans[blockIdx.x * 128 + tid];
    }

    const int len0 = lens[b0];
    const int len1 = lens[b1];
    const int len  = g ? len1 : len0;
    const int last = (len - 1) > 0 ? (len - 1) : 0;
    const int la0  = (len0 - 1) > 0 ? (len0 - 1) : 0;
    const int la1  = (len1 - 1) > 0 ? (len1 - 1) : 0;
    const int lmax = la0 > la1 ? la0 : la1;

    const int* tg = tags + (size_t)b * TT;
    const float* in_b = inputs + (size_t)b * TT * NS;

    // ---------------- sequence score (group-local) ----------------
    float sc = 0.f;
    for (int t = j; t < TT; t += NS) {
        if (t < len) {
            int yt = tg[t];
            sc += __ldg(&in_b[(size_t)t * NS + yt]);
            if (t >= 1) sc += __ldg(&trans[tg[t - 1] * NS + yt]);
        }
    }
    #pragma unroll
    for (int o = 16; o; o >>= 1) sc += __shfl_xor_sync(0xffffffffu, sc, o);
    if (lane == 0) red[g][wg] = sc;
    __syncthreads();
    const float seq_score = red[g][0] + red[g][1];
    __syncthreads();

    // ---------------- E column j, packed f32x2 pairs over i ----------------
    unsigned long long e2[NS / 2];
    #pragma unroll
    for (int k = 0; k < NS / 2; ++k) {
        unsigned lo = __float_as_uint(__expf(__ldg(&trans[(2 * k) * NS + j])));
        unsigned hi = __float_as_uint(__expf(__ldg(&trans[(2 * k + 1) * NS + j])));
        asm("mov.b64 %0, {%1, %2};" : "=l"(e2[k]) : "r"(lo), "r"(hi));
    }

    // ---------------- forward recurrence, scaled linear space ----------------
    // s_j(t) = exp(alpha_j(t) - M_t); renormalized so s_0 = 1 every step.
    float M = 0.f;
    float s_cur = __expf(in_b[j]);
    s_buf[g][0][j] = s_cur;

    // prefetch pe = exp(emit_j) depth 6 (off the serial chain)
    float pe0 = 1.f, pe1 = 1.f, pe2 = 1.f, pe3 = 1.f, pe4 = 1.f, pe5 = 1.f;
    if (1 <= last) pe0 = __expf(__ldg(&in_b[1 * NS + j]));
    if (2 <= last) pe1 = __expf(__ldg(&in_b[2 * NS + j]));
    if (3 <= last) pe2 = __expf(__ldg(&in_b[3 * NS + j]));
    if (4 <= last) pe3 = __expf(__ldg(&in_b[4 * NS + j]));
    if (5 <= last) pe4 = __expf(__ldg(&in_b[5 * NS + j]));
    if (6 <= last) pe5 = __expf(__ldg(&in_b[6 * NS + j]));

    int buf = 0;
    for (int t = 1; t <= lmax; ++t) {
        __syncthreads();
        if (t <= last) {
            // broadcast scalar s0: rcp + M-update overlap the dot
            const float s0 = s_buf[g][buf][0];
            const float r_inv = __frcp_rn(s0);
            M += __logf(s0);

            const float pe_c = pe0;
            pe0 = pe1; pe1 = pe2; pe2 = pe3; pe3 = pe4; pe4 = pe5;
            const int tn = t + 6;
            if (tn <= last) pe5 = __expf(__ldg(&in_b[(size_t)tn * NS + j]));

            const ulonglong2* p4 = (const ulonglong2*)s_buf[g][buf];
            unsigned long long a0 = 0ull, a1 = 0ull, a2 = 0ull, a3 = 0ull;
            #pragma unroll
            for (int m = 0; m < 16; m += 4) {
                ulonglong2 va = p4[m + 0];
                ulonglong2 vb = p4[m + 1];
                ulonglong2 vc = p4[m + 2];
                ulonglong2 vd = p4[m + 3];
                FMA2(a0, va.x, e2[2 * m + 0]); FMA2(a1, va.y, e2[2 * m + 1]);
                FMA2(a2, vb.x, e2[2 * m + 2]); FMA2(a3, vb.y, e2[2 * m + 3]);
                FMA2(a0, vc.x, e2[2 * m + 4]); FMA2(a1, vc.y, e2[2 * m + 5]);
                FMA2(a2, vd.x, e2[2 * m + 6]); FMA2(a3, vd.y, e2[2 * m + 7]);
            }
            unsigned long long c0, c1, c2;
            ADD2(c0, a0, a1);
            ADD2(c1, a2, a3);
            ADD2(c2, c0, c1);
            unsigned lo, hi;
            UNPACK2(lo, hi, c2);
            const float acc = __uint_as_float(lo) + __uint_as_float(hi);

            s_cur = acc * (pe_c * r_inv);
            s_buf[g][buf ^ 1][j] = s_cur;
        }
        buf ^= 1;
    }

    // alpha_j(last) = log(s_j) + M
    const float alpha = __logf(s_cur) + M;

    // ---------------- final logsumexp over 64 states (group-local) ----------------
    float mx = alpha;
    #pragma unroll
    for (int o = 16; o; o >>= 1)
        mx = fmaxf(mx, __shfl_xor_sync(0xffffffffu, mx, o));
    if (lane == 0) red[g][wg] = mx;
    __syncthreads();
    mx = fmaxf(red[g][0], red[g][1]);
    __syncthreads();

    float s = __expf(alpha - mx);
    #pragma unroll
    for (int o = 16; o; o >>= 1)
        s += __shfl_xor_sync(0xffffffffu, s, o);
    if (lane == 0) red[g][wg] = s;
    __syncthreads();
    s = red[g][0] + red[g][1];

    if (j == 0) out[b] = seq_score - (mx + __logf(s));
}

extern "C" void kernel_launch(void* const* d_in, const int* in_sizes, int n_in,
                              void* d_out, int out_size) {
    const float* inputs = (const float*)d_in[0];   // [B,T,N] f32
    const float* trans  = (const float*)d_in[1];   // [N,N]   f32
    const int*   tags   = (const int*)d_in[2];     // [B,T]   i32
    const int*   lens   = (const int*)d_in[3];     // [B]     i32
    float* out = (float*)d_out;

    const int write_trans = (out_size >= BB + NS * NS) ? 1 : 0;
    rank_kernel<<<1, BB>>>(lens);
    crf_kernel<<<BB / 2, 128>>>(inputs, trans, tags, lens, out, write_trans);
}

// round 6
// speedup vs baseline: 1.4768x; 1.0162x over previous
#include <cuda_runtime.h>

#define BB 512
#define TT 512
#define NS 64

// sm_103a packed fp32 pipe: 2 full-precision fp32 FMAs / ADDs per instruction
#define FMA2(acc, p, e) \
    asm("fma.rn.f32x2 %0, %1, %2, %0;" : "+l"(acc) : "l"(p), "l"(e))
#define ADD2(out, a, b) \
    asm("add.rn.f32x2 %0, %1, %2;" : "=l"(out) : "l"(a), "l"(b))
#define UNPACK2(lo, hi, v) \
    asm("mov.b64 {%0, %1}, %2;" : "=r"(lo), "=r"(hi) : "l"(v))

// One block = one batch chain. 128 threads: thread pair (2j, 2j+1) owns state
// j; half h sums i in [32h, 32h+32) (16 FMA2), combined by shfl_xor(1).
// 4 warps share each step's issue load; one plain __syncthreads per step.
__global__ __launch_bounds__(128) void crf_kernel(
    const float* __restrict__ inputs,   // [B,T,N]
    const float* __restrict__ trans,    // [N,N]
    const int*   __restrict__ tags,    // [B,T]
    const int*   __restrict__ lens,    // [B]
    float*       __restrict__ out,     // [B] ll, then [N*N] trans copy
    int write_trans)
{
    const int tid  = threadIdx.x;
    const int j    = tid >> 1;        // owned state 0..63
    const int h    = tid & 1;         // i-half
    const int w    = tid >> 5;        // warp
    const int lane = tid & 31;
    const int b    = blockIdx.x;

    __shared__ __align__(16) float sb0[NS], sb1[NS];
    __shared__ float red[4];

    if (write_trans && b < 32) {
        out[BB + b * 128 + tid] = trans[b * 128 + tid];
    }

    const int len  = lens[b];
    const int last = (len - 1) > 0 ? (len - 1) : 0;

    const int* tg = tags + (size_t)b * TT;
    const float* in_b = inputs + (size_t)b * TT * NS;

    // ---------------- sequence score ----------------
    float sc = 0.f;
    #pragma unroll
    for (int t = tid; t < TT; t += 128) {
        if (t < len) {
            int yt = tg[t];
            sc += __ldg(&in_b[(size_t)t * NS + yt]);
            if (t >= 1) sc += __ldg(&trans[tg[t - 1] * NS + yt]);
        }
    }
    #pragma unroll
    for (int o = 16; o; o >>= 1) sc += __shfl_xor_sync(0xffffffffu, sc, o);
    if (lane == 0) red[w] = sc;
    __syncthreads();
    const float seq_score = (red[0] + red[1]) + (red[2] + red[3]);
    __syncthreads();

    // ---- E quarter-column: rows 32h..32h+31 of column j, f32x2 row pairs ----
    unsigned long long e2[16];
    #pragma unroll
    for (int p = 0; p < 16; ++p) {
        const int i = 32 * h + 2 * p;
        unsigned lo = __float_as_uint(__expf(__ldg(&trans[i * NS + j])));
        unsigned hi = __float_as_uint(__expf(__ldg(&trans[(i + 1) * NS + j])));
        asm("mov.b64 %0, {%1, %2};" : "=l"(e2[p]) : "r"(lo), "r"(hi));
    }

    // ---------------- forward recurrence, scaled linear space ----------------
    float M = 0.f;
    float s_cur = __expf(in_b[j]);
    if (h == 0) sb0[j] = s_cur;

    // pe pipeline, depth 4: pe[k] = exp(emit[t+k][j])
    float pe0 = 1.f, pe1 = 1.f, pe2c = 1.f, pe3 = 1.f;
    if (1 <= last) pe0  = __expf(__ldg(&in_b[1 * NS + j]));
    if (2 <= last) pe1  = __expf(__ldg(&in_b[2 * NS + j]));
    if (3 <= last) pe2c = __expf(__ldg(&in_b[3 * NS + j]));
    if (4 <= last) pe3  = __expf(__ldg(&in_b[4 * NS + j]));

#define STEP(SRC, DST, PE)                                                    \
    do {                                                                      \
        __syncthreads();                                                      \
        const float s0 = (SRC)[0];                                            \
        const float r_inv = __frcp_rn(s0);                                    \
        M += __logf(s0);                                                      \
        const ulonglong2* p4 = (const ulonglong2*)(SRC) + (h << 3);           \
        unsigned long long a0 = 0ull, a1 = 0ull;                              \
        _Pragma("unroll")                                                     \
        for (int m = 0; m < 8; ++m) {                                         \
            const ulonglong2 v = p4[m];                                       \
            FMA2(a0, v.x, e2[2 * m + 0]);                                     \
            FMA2(a1, v.y, e2[2 * m + 1]);                                     \
        }                                                                     \
        ADD2(a0, a0, a1);                                                     \
        unsigned lo_, hi_;                                                    \
        UNPACK2(lo_, hi_, a0);                                                \
        float d = __uint_as_float(lo_) + __uint_as_float(hi_);                \
        d += __shfl_xor_sync(0xffffffffu, d, 1);                              \
        s_cur = d * ((PE) * r_inv);                                           \
        if (h == 0) (DST)[j] = s_cur;                                         \
    } while (0)

    int t = 1;
    for (; t + 1 <= last; t += 2) {
        STEP(sb0, sb1, pe0);
        STEP(sb1, sb0, pe1);
        pe0 = pe2c;
        pe1 = pe3;
        pe2c = (t + 4 <= last) ? __expf(__ldg(&in_b[(size_t)(t + 4) * NS + j])) : 1.f;
        pe3  = (t + 5 <= last) ? __expf(__ldg(&in_b[(size_t)(t + 5) * NS + j])) : 1.f;
    }
    if (t <= last) {
        STEP(sb0, sb1, pe0);
    }
#undef STEP

    // alpha_j(last) = log(s_j) + M
    const float alpha = __logf(s_cur) + M;

    // ---------------- final logsumexp over 64 states ----------------
    float mx = alpha;   // duplicates across h are harmless for max
    #pragma unroll
    for (int o = 16; o; o >>= 1)
        mx = fmaxf(mx, __shfl_xor_sync(0xffffffffu, mx, o));
    if (lane == 0) red[w] = mx;
    __syncthreads();
    mx = fmaxf(fmaxf(red[0], red[1]), fmaxf(red[2], red[3]));
    __syncthreads();

    float s = (h == 0) ? __expf(alpha - mx) : 0.f;  // count each state once
    #pragma unroll
    for (int o = 16; o; o >>= 1)
        s += __shfl_xor_sync(0xffffffffu, s, o);
    if (lane == 0) red[w] = s;
    __syncthreads();
    s = (red[0] + red[1]) + (red[2] + red[3]);

    if (tid == 0) out[b] = seq_score - (mx + __logf(s));
}

extern "C" void kernel_launch(void* const* d_in, const int* in_sizes, int n_in,
                              void* d_out, int out_size) {
    const float* inputs = (const float*)d_in[0];   // [B,T,N] f32
    const float* trans  = (const float*)d_in[1];   // [N,N]   f32
    const int*   tags   = (const int*)d_in[2];     // [B,T]   i32
    const int*   lens   = (const int*)d_in[3];     // [B]     i32
    float* out = (float*)d_out;

    const int write_trans = (out_size >= BB + NS * NS) ? 1 : 0;
    crf_kernel<<<BB, 128>>>(inputs, trans, tags, lens, out, write_trans);
}

// round 7
// speedup vs baseline: 2.7863x; 1.8867x over previous
#include <cuda_runtime.h>

#define BB 512
#define TT 512
#define NS 64

// sm_103a packed fp32 pipe: 2 full-precision fp32 FMAs / ADDs per instruction
#define FMA2(acc, p, e) \
    asm("fma.rn.f32x2 %0, %1, %2, %0;" : "+l"(acc) : "l"(p), "l"(e))
#define ADD2(out, a, b) \
    asm("add.rn.f32x2 %0, %1, %2;" : "=l"(out) : "l"(a), "l"(b))
#define UNPACK2(lo, hi, v) \
    asm("mov.b64 {%0, %1}, %2;" : "=r"(lo), "=r"(hi) : "l"(v))

__device__ int d_perm[BB];

// Rank batches by sequence length (descending): longest chains first.
__global__ void rank_kernel(const int* __restrict__ lens) {
    __shared__ int L[BB];
    const int b = threadIdx.x;
    L[b] = lens[b];
    __syncthreads();
    const int myl = L[b];
    int r = 0;
    #pragma unroll 8
    for (int i = 0; i < BB; ++i) {
        const int li = L[i];
        r += (li > myl) || (li == myl && i < b);
    }
    d_perm[r] = b;
}

// One block (64 threads, 2 warps) = one batch chain; thread j owns state j
// and computes the full 64-wide dot (32 FMA2). Renormalization by an exact
// power of two derived from s0's exponent bits: no MUFU rcp/log in the loop.
__global__ __launch_bounds__(64) void crf_kernel(
    const float* __restrict__ inputs,   // [B,T,N]
    const float* __restrict__ trans,    // [N,N]
    const int*   __restrict__ tags,    // [B,T]
    const int*   __restrict__ lens,    // [B]
    float*       __restrict__ out,     // [B] ll, then [N*N] trans copy
    int write_trans)
{
    const int bb   = blockIdx.x;
    const int b    = d_perm[bb];
    const int j    = threadIdx.x;   // state index 0..63
    const int w    = j >> 5;
    const int lane = j & 31;

    __shared__ __align__(16) float sb0[NS], sb1[NS];
    __shared__ float red[2];

    if (write_trans && bb < NS) {
        out[BB + bb * NS + j] = trans[bb * NS + j];
    }

    const int len  = lens[b];
    const int last = (len - 1) > 0 ? (len - 1) : 0;

    const int* tg = tags + (size_t)b * TT;
    const float* in_b = inputs + (size_t)b * TT * NS;

    // ---------------- sequence score ----------------
    float sc = 0.f;
    for (int t = j; t < TT; t += NS) {
        if (t < len) {
            int yt = tg[t];
            sc += __ldg(&in_b[(size_t)t * NS + yt]);
            if (t >= 1) sc += __ldg(&trans[tg[t - 1] * NS + yt]);
        }
    }
    #pragma unroll
    for (int o = 16; o; o >>= 1) sc += __shfl_xor_sync(0xffffffffu, sc, o);
    if (lane == 0) red[w] = sc;
    __syncthreads();
    const float seq_score = red[0] + red[1];
    __syncthreads();

    // ---------------- E column j, packed f32x2 pairs over i ----------------
    unsigned long long e2[NS / 2];
    #pragma unroll
    for (int k = 0; k < NS / 2; ++k) {
        unsigned lo = __float_as_uint(__expf(__ldg(&trans[(2 * k) * NS + j])));
        unsigned hi = __float_as_uint(__expf(__ldg(&trans[(2 * k + 1) * NS + j])));
        asm("mov.b64 %0, {%1, %2};" : "=l"(e2[k]) : "r"(lo), "r"(hi));
    }

    // ---------------- forward recurrence, scaled linear space ----------------
    // s_j(t) = exp(alpha_j(t)) * 2^{-Mk_t}; renorm each step by the exact
    // power of two 2^{-(e(s0)-127)} so s0 stays in [1,2). Mk exact integer.
    int Mk = 0;
    float s_cur = __expf(in_b[j]);
    sb0[j] = s_cur;

    // pe pipeline depth 6: pe[k] = exp(emit[t+k][j])
    float pe0 = 1.f, pe1 = 1.f, pe2 = 1.f, pe3 = 1.f, pe4 = 1.f, pe5 = 1.f;
    if (1 <= last) pe0 = __expf(__ldg(&in_b[1 * NS + j]));
    if (2 <= last) pe1 = __expf(__ldg(&in_b[2 * NS + j]));
    if (3 <= last) pe2 = __expf(__ldg(&in_b[3 * NS + j]));
    if (4 <= last) pe3 = __expf(__ldg(&in_b[4 * NS + j]));
    if (5 <= last) pe4 = __expf(__ldg(&in_b[5 * NS + j]));
    if (6 <= last) pe5 = __expf(__ldg(&in_b[6 * NS + j]));

#define STEP(SRC, DST, PE)                                                    \
    do {                                                                      \
        __syncthreads();                                                      \
        const unsigned s0b = __float_as_uint((SRC)[0]);                       \
        const unsigned ke  = s0b >> 23;                                       \
        Mk += (int)ke - 127;                                                  \
        const float r_inv = __uint_as_float((254u - ke) << 23);               \
        const ulonglong2* p4 = (const ulonglong2*)(SRC);                      \
        unsigned long long a0 = 0ull, a1 = 0ull, a2 = 0ull, a3 = 0ull;        \
        unsigned long long a4 = 0ull, a5 = 0ull, a6 = 0ull, a7 = 0ull;        \
        _Pragma("unroll")                                                     \
        for (int m = 0; m < 4; ++m) {                                         \
            const ulonglong2 va = p4[4 * m + 0];                              \
            const ulonglong2 vb = p4[4 * m + 1];                              \
            const ulonglong2 vc = p4[4 * m + 2];                              \
            const ulonglong2 vd = p4[4 * m + 3];                              \
            FMA2(a0, va.x, e2[8 * m + 0]); FMA2(a1, va.y, e2[8 * m + 1]);     \
            FMA2(a2, vb.x, e2[8 * m + 2]); FMA2(a3, vb.y, e2[8 * m + 3]);     \
            FMA2(a4, vc.x, e2[8 * m + 4]); FMA2(a5, vc.y, e2[8 * m + 5]);     \
            FMA2(a6, vd.x, e2[8 * m + 6]); FMA2(a7, vd.y, e2[8 * m + 7]);     \
        }                                                                     \
        ADD2(a0, a0, a1); ADD2(a2, a2, a3);                                   \
        ADD2(a4, a4, a5); ADD2(a6, a6, a7);                                   \
        ADD2(a0, a0, a2); ADD2(a4, a4, a6);                                   \
        ADD2(a0, a0, a4);                                                     \
        unsigned lo_, hi_;                                                    \
        UNPACK2(lo_, hi_, a0);                                                \
        const float acc = __uint_as_float(lo_) + __uint_as_float(hi_);        \
        s_cur = acc * ((PE) * r_inv);                                         \
        (DST)[j] = s_cur;                                                     \
    } while (0)

    int t = 1;
    for (; t + 1 <= last; t += 2) {
        STEP(sb0, sb1, pe0);
        STEP(sb1, sb0, pe1);
        pe0 = pe2; pe1 = pe3; pe2 = pe4; pe3 = pe5;
        pe4 = (t + 6 <= last) ? __expf(__ldg(&in_b[(size_t)(t + 6) * NS + j])) : 1.f;
        pe5 = (t + 7 <= last) ? __expf(__ldg(&in_b[(size_t)(t + 7) * NS + j])) : 1.f;
    }
    if (t <= last) {
        STEP(sb0, sb1, pe0);
    }
#undef STEP

    // alpha_j(last) = log(s_j) + Mk*ln2
    const float alpha = __logf(s_cur) + (float)Mk * 0.6931471805599453f;

    // ---------------- final logsumexp over states ----------------
    float mx = alpha;
    #pragma unroll
    for (int o = 16; o; o >>= 1)
        mx = fmaxf(mx, __shfl_xor_sync(0xffffffffu, mx, o));
    if (lane == 0) red[w] = mx;
    __syncthreads();
    mx = fmaxf(red[0], red[1]);
    __syncthreads();

    float s = __expf(alpha - mx);
    #pragma unroll
    for (int o = 16; o; o >>= 1)
        s += __shfl_xor_sync(0xffffffffu, s, o);
    if (lane == 0) red[w] = s;
    __syncthreads();
    s = red[0] + red[1];

    if (j == 0) out[b] = seq_score - (mx + __logf(s));
}

extern "C" void kernel_launch(void* const* d_in, const int* in_sizes, int n_in,
                              void* d_out, int out_size) {
    const float* inputs = (const float*)d_in[0];   // [B,T,N] f32
    const float* trans  = (const float*)d_in[1];   // [N,N]   f32
    const int*   tags   = (const int*)d_in[2];     // [B,T]   i32
    const int*   lens   = (const int*)d_in[3];     // [B]     i32
    float* out = (float*)d_out;

    const int write_trans = (out_size >= BB + NS * NS) ? 1 : 0;
    rank_kernel<<<1, BB>>>(lens);
    crf_kernel<<<BB, NS>>>(inputs, trans, tags, lens, out, write_trans);
}